// round 7
// baseline (speedup 1.0000x reference)
#include <cuda_runtime.h>

#define TT 64
#define FULL 0xffffffffu

__host__ __device__ constexpr int cnotF(int k) {
    int b0 = k & 1, b1 = (k >> 1) & 1, b2 = (k >> 2) & 1, b3 = (k >> 3) & 1;
    b1 ^= b0; b2 ^= b1; b3 ^= b2; b0 ^= b3;
    return b0 | (b1 << 1) | (b2 << 2) | (b3 << 3);
}
__host__ __device__ constexpr int cnotFinv(int s) {
    int r = 0;
    for (int k = 0; k < 16; ++k) if (cnotF(k) == s) r = k;
    return r;
}
__host__ __device__ constexpr int popc4(int k) {
    return (k & 1) + ((k >> 1) & 1) + ((k >> 2) & 1) + ((k >> 3) & 1);
}

__device__ __forceinline__ float sx(float v, int m) { return __shfl_xor_sync(FULL, v, m); }
__device__ __forceinline__ float tanhap(float v) {
    float r;
    asm("tanh.approx.f32 %0, %1;" : "=f"(r) : "f"(v));
    return r;
}
// runtime-index pick from a 4-register array (compiles to SELs, no local mem)
__device__ __forceinline__ float pick4(const float a[4], int j) {
    float x = (j & 2) ? a[2] : a[0];
    float y = (j & 2) ? a[3] : a[1];
    return (j & 1) ? y : x;
}

__global__ void __launch_bounds__(128, 1)
qlstm16s(const float* __restrict__ x,
         const float* __restrict__ w_in,  const float* __restrict__ b_in,
         const float* __restrict__ w_out, const float* __restrict__ b_out,
         const float* __restrict__ wq_f,  const float* __restrict__ wq_i,
         const float* __restrict__ wq_u,  const float* __restrict__ wq_o,
         const float* __restrict__ w_fc,  const float* __restrict__ b_fc,
         float* __restrict__ out, int B)
{
    const int tid = blockIdx.x * 128 + threadIdx.x;
    const int e0  = tid >> 4;
    const int gl  = tid & 15;         // lane in 16-group
    const int g   = gl >> 2;          // gate (f,i,u,o)
    const int sub = gl & 3;           // slot bits (3,2)
    const int lane = threadIdx.x & 31;
    const int b16 = lane & ~15;
    const int base4 = lane & ~3;      // gate-aligned 4-block base
    const int grp = threadIdx.x >> 4; // group in block (0..7)
    const int e   = (e0 < B) ? e0 : B - 1;

    // ---------------- pre-pass: xproj -> shared (h-independent) ----------------
    __shared__ float4 sxp[8][TT];
    {
        const float* xe = x + (long)e * TT * 32;
        float acc[4][4];
#pragma unroll
        for (int i = 0; i < 4; ++i)
#pragma unroll
            for (int w = 0; w < 4; ++w) acc[i][w] = 0.f;
#pragma unroll
        for (int c = 0; c < 8; ++c) {
            float4 wv[4];
#pragma unroll
            for (int w = 0; w < 4; ++w)
                wv[w] = *reinterpret_cast<const float4*>(&w_in[w * 40 + 8 + 4 * c]);
#pragma unroll
            for (int i = 0; i < 4; ++i) {
                float4 xv = *reinterpret_cast<const float4*>(&xe[(gl * 4 + i) * 32 + 4 * c]);
#pragma unroll
                for (int w = 0; w < 4; ++w) {
                    acc[i][w] = fmaf(xv.x, wv[w].x, acc[i][w]);
                    acc[i][w] = fmaf(xv.y, wv[w].y, acc[i][w]);
                    acc[i][w] = fmaf(xv.z, wv[w].z, acc[i][w]);
                    acc[i][w] = fmaf(xv.w, wv[w].w, acc[i][w]);
                }
            }
        }
#pragma unroll
        for (int i = 0; i < 4; ++i)
            sxp[grp][gl * 4 + i] = make_float4(0.5f * acc[i][0], 0.5f * acc[i][1],
                                               0.5f * acc[i][2], 0.5f * acc[i][3]);
    }
    __syncthreads();

    const float* wq = (g == 0) ? wq_f : (g == 1) ? wq_i : (g == 2) ? wq_u : wq_o;

    // ---- circuit constants ----
    float hw0[4], C[4], Sv[4];
#pragma unroll
    for (int w = 0; w < 4; ++w) {
        hw0[w] = 0.5f * (__ldg(&wq[w]) + __ldg(&b_in[w]));
        float a = 0.5f * __ldg(&wq[4 + w]);
        C[w] = cosf(a); Sv[w] = sinf(a);
    }
    const float hw0own = pick4(hw0, sub);   // bias for own wire (resolved once)

    // h-projection weights for own 2 comps (pre-scaled 0.5)
    float Wh2[4][2];
#pragma unroll
    for (int w = 0; w < 4; ++w)
#pragma unroll
        for (int j = 0; j < 2; ++j)
            Wh2[w][j] = 0.5f * __ldg(&w_in[w * 40 + 2 * sub + j]);

    // output proj rows, Hadamard chars + activation prescale folded in
    const float chiP = (popc4(sub) & 1) ? -1.f : 1.f;
    const float chiB = (sub & 1) ? -1.f : 1.f;
    const float chi[4] = {chiP, 1.f, chiB, chiP};
    const float asc = (g == 2) ? 1.f : 0.5f;
    const float A1  = (g == 2) ? 1.f : 0.5f;
    const float A2  = (g == 2) ? 0.f : 0.5f;
    float Wo[2][4], bo[2];
#pragma unroll
    for (int i = 0; i < 2; ++i) {
        bo[i] = asc * __ldg(&b_out[2 * sub + i]);
#pragma unroll
        for (int w = 0; w < 4; ++w)
            Wo[i][w] = asc * chi[w] * __ldg(&w_out[(2 * sub + i) * 4 + w]);
    }

    // ---- per-lane sign tables (slots s = 4*sub + u) ----
    const int FLIPT[4] = {0, 12, 11, 7};   // Finv(4*sub)
    const int flip = FLIPT[sub];
    float sg3[4], t0[4], b1s[4], b2s[4];
#pragma unroll
    for (int u = 0; u < 4; ++u) {
        const int cls  = popc4(cnotFinv(u) ^ flip) & 3;
        const int c3p  = popc4(cnotFinv(u) ^ flip ^ 11) & 3;
        const int c0p  = popc4(cnotFinv(u ^ 1) ^ flip) & 3;
        const int c1p  = popc4(cnotFinv(u ^ 2) ^ flip) & 3;
        const int c2p  = popc4(cnotFinv(u) ^ flip ^ 12) & 3;
        sg3[u] = (((c3p + 1 - cls) & 3) == 0) ?  Sv[3] : -Sv[3];
        t0 [u] = (((c0p - cls) & 3) == 0)     ? -Sv[0] :  Sv[0];
        b1s[u] = (((c1p - cls) & 3) == 0)     ?  Sv[1] : -Sv[1];
        b2s[u] = (((c2p - cls) & 3) == 0)     ?  Sv[2] : -Sv[2];
    }
    const bool f0 = flip & 1, f1 = flip & 2, f2 = flip & 4, f3 = flip & 8;
    const int s1 = sub ^ 1, s2 = sub ^ 2, s3 = sub ^ 3;

    float cc0 = 0.f, cc1 = 0.f;       // own c comps {2sub, 2sub+1}
    float h0  = 0.f, h1  = 0.f;       // own h comps {2sub, 2sub+1}

#pragma unroll 1
    for (int t = 0; t < TT; ++t) {
        // ---- own-wire x-part (off critical chain) ----
        float4 xq = sxp[grp][t];
        const float xarr[4] = {xq.x, xq.y, xq.z, xq.w};
        const float xko = pick4(xarr, sub) + hw0own;

        // ---- h-partials for all wires; transpose-reduce to own-wire angle ----
        float pw[4];
#pragma unroll
        for (int w = 0; w < 4; ++w)
            pw[w] = fmaf(h0, Wh2[w][0], h1 * Wh2[w][1]);
        float v1 = pick4(pw, s1), v2 = pick4(pw, s2), v3 = pick4(pw, s3);
        float ang = ((pick4(pw, sub) + sx(v1, 1)) + (sx(v2, 2) + sx(v3, 3))) + xko;

        // ---- one sincos per lane; broadcast in static wire order ----
        float mys, myc;
        __sincosf(ang, &mys, &myc);
        float cw[4], sw[4];
#pragma unroll
        for (int w = 0; w < 4; ++w) {
            cw[w] = __shfl_sync(FULL, myc, base4 | w);
            sw[w] = __shfl_sync(FULL, mys, base4 | w);
        }

        const float ec0 = f0 ? sw[0] : cw[0], es0 = f0 ? cw[0] : sw[0];
        const float ec1 = f1 ? sw[1] : cw[1], es1 = f1 ? cw[1] : sw[1];
        const float ec2 = f2 ? sw[2] : cw[2], es2 = f2 ? cw[2] : sw[2];
        const float ec3 = f3 ? sw[3] : cw[3];

        // ---- product build (Finv(0..3)={0,3,6,5}, bit3=0) ----
        const float mc = ec2 * ec3, ms = es2 * ec3;
        float r0 = (ec0 * ec1) * mc;
        float r1 = (es0 * es1) * mc;
        float r2 = (ec0 * es1) * ms;
        float r3 = (es0 * ec1) * ms;

        // ---- RX wire3 (mask 8): cross-lane sx(,2), pure-real Givens ----
        {
            float p0 = sx(r0, 2), p1 = sx(r1, 2), p2 = sx(r2, 2), p3 = sx(r3, 2);
            r0 = fmaf(C[3], r0, sg3[0] * p0);
            r1 = fmaf(C[3], r1, sg3[1] * p1);
            r2 = fmaf(C[3], r2, sg3[2] * p2);
            r3 = fmaf(C[3], r3, sg3[3] * p3);
        }
        // ---- RX wire0 (mask 1): local, pure -> complex ----
        float Re[4], Im[4];
        Re[0] = C[0] * r0;  Im[0] = t0[0] * r1;
        Re[1] = C[0] * r1;  Im[1] = t0[1] * r0;
        Re[2] = C[0] * r2;  Im[2] = t0[2] * r3;
        Re[3] = C[0] * r3;  Im[3] = t0[3] * r2;

        // ---- RX wire1 (mask 2): local complex, pairs (0,2),(1,3) ----
#pragma unroll
        for (int u = 0; u < 2; ++u) {
            const int v = u | 2;
            float ar = Re[u], ai = Im[u], br = Re[v], bi = Im[v];
            Re[u] = fmaf(b1s[u], bi, C[1] * ar); Im[u] = fmaf(-b1s[u], br, C[1] * ai);
            Re[v] = fmaf(b1s[v], ai, C[1] * br); Im[v] = fmaf(-b1s[v], ar, C[1] * bi);
        }
        // ---- RX wire2 (mask 4): cross-lane sx(,1), complex ----
#pragma unroll
        for (int u = 0; u < 4; ++u) {
            float rp = sx(Re[u], 1), ip = sx(Im[u], 1);
            Re[u] = fmaf(b2s[u], ip, C[2] * Re[u]);
            Im[u] = fmaf(-b2s[u], rp, C[2] * Im[u]);
        }

        // ---- probabilities + Walsh partials (parallel shfl form) ----
        float q0 = fmaf(Re[0], Re[0], Im[0] * Im[0]);
        float q1 = fmaf(Re[1], Re[1], Im[1] * Im[1]);
        float q2 = fmaf(Re[2], Re[2], Im[2] * Im[2]);
        float q3 = fmaf(Re[3], Re[3], Im[3] * Im[3]);
        float d0 = q0 - q2, d1 = q1 - q3;
        float P0 = d0 + d1, P1 = d0 - d1;

        float Aq = sx(P0, 1), Bq = sx(P0, 2), Cq = sx(P0, 3);
        float Dq = sx(P1, 1), Eq = sx(P1, 2), Fq = sx(P1, 3);
        float ex0 = (P0 - Aq) - (Bq - Cq);
        float ex1 = (P1 + Dq) + (Eq + Fq);
        float em  = P1 - Dq, ep = Eq - Fq;
        float ex2 = em + ep;
        float ex3 = em - ep;

        // ---- activations for own 2 comps (tree-ified gv) ----
        float ga0 = fmaf(ex1, Wo[0][1], fmaf(ex0, Wo[0][0], bo[0]));
        float gb0 = fmaf(ex3, Wo[0][3], ex2 * Wo[0][2]);
        float ga1 = fmaf(ex1, Wo[1][1], fmaf(ex0, Wo[1][0], bo[1]));
        float gb1 = fmaf(ex3, Wo[1][3], ex2 * Wo[1][2]);
        float act0 = fmaf(A1, tanhap(ga0 + gb0), A2);
        float act1 = fmaf(A1, tanhap(ga1 + gb1), A2);

        // ---- gather f,i,u,o; cell update ----
        {
            const int s0 = b16 + sub;
            float fv0 = __shfl_sync(FULL, act0, s0);
            float fv1 = __shfl_sync(FULL, act1, s0);
            float iv0 = __shfl_sync(FULL, act0, s0 + 4);
            float iv1 = __shfl_sync(FULL, act1, s0 + 4);
            float uv0 = __shfl_sync(FULL, act0, s0 + 8);
            float uv1 = __shfl_sync(FULL, act1, s0 + 8);
            float ov0 = __shfl_sync(FULL, act0, s0 + 12);
            float ov1 = __shfl_sync(FULL, act1, s0 + 12);

            cc0 = fmaf(fv0, cc0, iv0 * uv0);
            cc1 = fmaf(fv1, cc1, iv1 * uv1);
            h0 = ov0 * tanhap(cc0);
            h1 = ov1 * tanhap(cc1);
        }
    }

    // ---- final projection (own comps; reduce over sub lanes) ----
    float p = h0 * __ldg(&w_fc[2 * sub]);
    p = fmaf(h1, __ldg(&w_fc[2 * sub + 1]), p);
    p += sx(p, 1);
    p += sx(p, 2);
    if (gl == 0 && e0 < B) out[e0] = p + __ldg(&b_fc[0]);
}

extern "C" void kernel_launch(void* const* d_in, const int* in_sizes, int n_in,
                              void* d_out, int out_size) {
    const float* x     = (const float*)d_in[0];
    const float* w_in  = (const float*)d_in[1];
    const float* b_in  = (const float*)d_in[2];
    const float* w_out = (const float*)d_in[3];
    const float* b_out = (const float*)d_in[4];
    const float* wq_f  = (const float*)d_in[5];
    const float* wq_i  = (const float*)d_in[6];
    const float* wq_u  = (const float*)d_in[7];
    const float* wq_o  = (const float*)d_in[8];
    const float* w_fc  = (const float*)d_in[9];
    const float* b_fc  = (const float*)d_in[10];

    int B = in_sizes[0] / (TT * 32);
    int threads = B * 16;
    int blocks = (threads + 127) / 128;
    qlstm16s<<<blocks, 128>>>(x, w_in, b_in, w_out, b_out,
                              wq_f, wq_i, wq_u, wq_o, w_fc, b_fc,
                              (float*)d_out, B);
}

// round 8
// speedup vs baseline: 1.0986x; 1.0986x over previous
#include <cuda_runtime.h>

#define TT 64
#define FULL 0xffffffffu

__host__ __device__ constexpr int popc4(int k) {
    return (k & 1) + ((k >> 1) & 1) + ((k >> 2) & 1) + ((k >> 3) & 1);
}
// k(sub,u) for layout sub=(bit3,bit0), u=(bit2,bit1); Finv basis {1,2,4,8}->{3,6,12,11}
__host__ __device__ constexpr int kof(int sub_, int u_) {
    return ((sub_ & 1) ? 3 : 0) ^ ((u_ & 1) ? 6 : 0) ^ ((u_ & 2) ? 12 : 0) ^ ((sub_ & 2) ? 11 : 0);
}

__device__ __forceinline__ float sx(float v, int m) { return __shfl_xor_sync(FULL, v, m); }
__device__ __forceinline__ float tanhap(float v) {
    float r;
    asm("tanh.approx.f32 %0, %1;" : "=f"(r) : "f"(v));
    return r;
}

__global__ void __launch_bounds__(128, 1)
qlstm4s(const float* __restrict__ x,
        const float* __restrict__ w_in,  const float* __restrict__ b_in,
        const float* __restrict__ w_out, const float* __restrict__ b_out,
        const float* __restrict__ wq_f,  const float* __restrict__ wq_i,
        const float* __restrict__ wq_u,  const float* __restrict__ wq_o,
        const float* __restrict__ w_fc,  const float* __restrict__ b_fc,
        float* __restrict__ out, int B)
{
    const int tid = blockIdx.x * 128 + threadIdx.x;
    const int e0  = tid >> 4;
    const int gl  = tid & 15;         // lane in 16-group
    const int g   = gl >> 2;          // gate (f,i,u,o)
    const int sub = gl & 3;           // slot bits (3,0)
    const int lane = threadIdx.x & 31;
    const int b16 = lane & ~15;
    const int grp = threadIdx.x >> 4; // group in block (0..7)
    const int e   = (e0 < B) ? e0 : B - 1;

    // ---------------- pre-pass: xproj -> shared (h-independent) ----------------
    __shared__ float4 sxp[8][TT];
    {
        const float* xe = x + (long)e * TT * 32;
        float acc[4][4];
#pragma unroll
        for (int i = 0; i < 4; ++i)
#pragma unroll
            for (int w = 0; w < 4; ++w) acc[i][w] = 0.f;
#pragma unroll
        for (int c = 0; c < 8; ++c) {
            float4 wv[4];
#pragma unroll
            for (int w = 0; w < 4; ++w)
                wv[w] = *reinterpret_cast<const float4*>(&w_in[w * 40 + 8 + 4 * c]);
#pragma unroll
            for (int i = 0; i < 4; ++i) {
                float4 xv = *reinterpret_cast<const float4*>(&xe[(gl * 4 + i) * 32 + 4 * c]);
#pragma unroll
                for (int w = 0; w < 4; ++w) {
                    acc[i][w] = fmaf(xv.x, wv[w].x, acc[i][w]);
                    acc[i][w] = fmaf(xv.y, wv[w].y, acc[i][w]);
                    acc[i][w] = fmaf(xv.z, wv[w].z, acc[i][w]);
                    acc[i][w] = fmaf(xv.w, wv[w].w, acc[i][w]);
                }
            }
        }
#pragma unroll
        for (int i = 0; i < 4; ++i)
            sxp[grp][gl * 4 + i] = make_float4(0.5f * acc[i][0], 0.5f * acc[i][1],
                                               0.5f * acc[i][2], 0.5f * acc[i][3]);
    }
    __syncthreads();

    const float* wq = (g == 0) ? wq_f : (g == 1) ? wq_i : (g == 2) ? wq_u : wq_o;

    // ---- circuit constants ----
    float hw0[4], C[4], Sv[4];
#pragma unroll
    for (int w = 0; w < 4; ++w) {
        hw0[w] = 0.5f * (__ldg(&wq[w]) + __ldg(&b_in[w]));
        float a = 0.5f * __ldg(&wq[4 + w]);
        C[w] = cosf(a); Sv[w] = sinf(a);
    }

    // h-projection weights for own 2 comps (pre-scaled 0.5)
    float Wh2[4][2];
#pragma unroll
    for (int w = 0; w < 4; ++w)
#pragma unroll
        for (int j = 0; j < 2; ++j)
            Wh2[w][j] = 0.5f * __ldg(&w_in[w * 40 + 2 * sub + j]);

    // output proj rows: new Walsh characters + activation prescale folded in
    const int sig0 = sub & 1, sig1 = (sub >> 1) & 1;
    const float chi0  = sig1 ? -1.f : 1.f;
    const float chi12 = sig0 ? -1.f : 1.f;
    const float chi3  = (sig0 ^ sig1) ? -1.f : 1.f;
    const float chi[4] = {chi0, chi12, chi12, chi3};
    const float asc = (g == 2) ? 1.f : 0.5f;
    const float A1c = (g == 2) ? 1.f : 0.5f;
    const float A2c = (g == 2) ? 0.f : 0.5f;
    float Wo[2][4], bo[2];
#pragma unroll
    for (int i = 0; i < 2; ++i) {
        bo[i] = asc * __ldg(&b_out[2 * sub + i]);
#pragma unroll
        for (int w = 0; w < 4; ++w)
            Wo[i][w] = asc * chi[w] * __ldg(&w_out[(2 * sub + i) * 4 + w]);
    }

    // ---- per-lane sign tables for new layout ----
    float sg3[4], sg3p[4], t0[4], b1s[4], b2s[4];
#pragma unroll
    for (int u = 0; u < 4; ++u) {
        const int k   = kof(sub, u);
        const int cls = popc4(k) & 3;
        sg3[u] = ((((popc4(k ^ 11) & 3) + 1 - cls) & 3) == 0) ?  Sv[3] : -Sv[3];
        const int kp   = kof(sub ^ 1, u);
        const int clsp = popc4(kp) & 3;
        sg3p[u] = ((((popc4(kp ^ 11) & 3) + 1 - clsp) & 3) == 0) ?  Sv[3] : -Sv[3];
        t0 [u] = ((((popc4(k ^ 3)  & 3) - cls) & 3) == 0) ? -Sv[0] :  Sv[0];
        b1s[u] = ((((popc4(k ^ 6)  & 3) - cls) & 3) == 0) ?  Sv[1] : -Sv[1];
        b2s[u] = ((((popc4(k ^ 12) & 3) - cls) & 3) == 0) ?  Sv[2] : -Sv[2];
    }
    // effective-factor swap flags: K0 = sig0*3 ^ sig1*11 -> bits {par,par,0,sig1}
    const bool f01 = (sig0 ^ sig1) != 0;
    const bool f3  = sig1 != 0;

    float cc0 = 0.f, cc1 = 0.f;       // own c comps {2sub, 2sub+1}
    float h0  = 0.f, h1  = 0.f;       // own h comps {2sub, 2sub+1}

#pragma unroll 1
    for (int t = 0; t < TT; ++t) {
        float4 xq = sxp[grp][t];
        const float xk[4] = {xq.x + hw0[0], xq.y + hw0[1], xq.z + hw0[2], xq.w + hw0[3]};

        // ---- S1: angle all-reduce in ONE stage (12 shfls) + local sincos ----
        float pw[4];
#pragma unroll
        for (int w = 0; w < 4; ++w)
            pw[w] = fmaf(h0, Wh2[w][0], h1 * Wh2[w][1]);
        float cw[4], swv[4];
#pragma unroll
        for (int w = 0; w < 4; ++w) {
            float p1 = sx(pw[w], 1), p2 = sx(pw[w], 2), p3 = sx(pw[w], 3);
            float ang = ((pw[w] + p1) + (p2 + p3)) + xk[w];
            __sincosf(ang, &swv[w], &cw[w]);
        }

        const float ec0 = f01 ? swv[0] : cw[0];
        const float ec1 = f01 ? swv[1] : cw[1], es1 = f01 ? cw[1] : swv[1];
        const float c2  = cw[2], s2 = swv[2];
        const float ec3 = f3 ? swv[3] : cw[3],  es3 = f3 ? cw[3] : swv[3];

        // ---- product build: r[u] = ec0 * T1(u0) * T2(u0^u1) * T3(u1) ----
        const float a01c = ec0 * ec1, a01s = ec0 * es1;
        const float m2c = c2 * ec3, m2s = s2 * ec3;
        const float m3s = s2 * es3, m3c = c2 * es3;
        float r0 = a01c * m2c;
        float r1 = a01s * m2s;
        float r2 = a01c * m3s;
        float r3 = a01s * m3c;

        // ---- S2: single exchange stage (12 shfls) -> wire3 + wire0 local ----
        float rm1[4], rm2[4], rm3[4];
        rm1[0] = sx(r0, 1); rm1[1] = sx(r1, 1); rm1[2] = sx(r2, 1); rm1[3] = sx(r3, 1);
        rm2[0] = sx(r0, 2); rm2[1] = sx(r1, 2); rm2[2] = sx(r2, 2); rm2[3] = sx(r3, 2);
        rm3[0] = sx(r0, 3); rm3[1] = sx(r1, 3); rm3[2] = sx(r2, 3); rm3[3] = sx(r3, 3);
        const float rr[4] = {r0, r1, r2, r3};
        float Re[4], Im[4];
#pragma unroll
        for (int u = 0; u < 4; ++u) {
            float w3  = fmaf(C[3], rr[u],  sg3[u]  * rm2[u]);   // own post-wire3
            float w3p = fmaf(C[3], rm1[u], sg3p[u] * rm3[u]);   // wire0-partner post-wire3
            Re[u] = C[0] * w3;
            Im[u] = t0[u] * w3p;
        }
        // ---- RX wire1 (local, pairs u^1): (0,1),(2,3) ----
#pragma unroll
        for (int u = 0; u < 4; u += 2) {
            const int v = u | 1;
            float ar = Re[u], ai = Im[u], br = Re[v], bi = Im[v];
            Re[u] = fmaf(b1s[u], bi, C[1] * ar); Im[u] = fmaf(-b1s[u], br, C[1] * ai);
            Re[v] = fmaf(b1s[v], ai, C[1] * br); Im[v] = fmaf(-b1s[v], ar, C[1] * bi);
        }
        // ---- RX wire2 (local, pairs u^2): (0,2),(1,3) ----
#pragma unroll
        for (int u = 0; u < 2; ++u) {
            const int v = u | 2;
            float ar = Re[u], ai = Im[u], br = Re[v], bi = Im[v];
            Re[u] = fmaf(b2s[u], bi, C[2] * ar); Im[u] = fmaf(-b2s[u], br, C[2] * ai);
            Re[v] = fmaf(b2s[v], ai, C[2] * br); Im[v] = fmaf(-b2s[v], ar, C[2] * bi);
        }

        // ---- probabilities + per-lane Walsh patterns ----
        float q0 = fmaf(Re[0], Re[0], Im[0] * Im[0]);
        float q1 = fmaf(Re[1], Re[1], Im[1] * Im[1]);
        float q2 = fmaf(Re[2], Re[2], Im[2] * Im[2]);
        float q3 = fmaf(Re[3], Re[3], Im[3] * Im[3]);
        float PA = (q0 - q1) - (q2 - q3);    // (-1)^(u0^u1)
        float PB = (q0 - q1) + (q2 - q3);    // (-1)^(u0)

        // ---- S3: Walsh cross-sub reduce, ONE stage (6 shfls) ----
        float A1 = sx(PA, 1), A2 = sx(PA, 2), A3 = sx(PA, 3);
        float B1 = sx(PB, 1), B2 = sx(PB, 2), B3 = sx(PB, 3);
        float ex0 = (PA + A1) - (A2 + A3);   // char (-1)^sig1 (in Wo)
        float ex1 = (PB - B1) + (B2 - B3);   // char (-1)^sig0
        float tA  = PA - A1, tB = A2 - A3;
        float ex2 = tA + tB;                 // char (-1)^sig0
        float ex3 = tA - tB;                 // char (-1)^(sig0^sig1)

        // ---- activations for own 2 comps ----
        float ga0 = fmaf(ex1, Wo[0][1], fmaf(ex0, Wo[0][0], bo[0]));
        float gb0 = fmaf(ex3, Wo[0][3], ex2 * Wo[0][2]);
        float ga1 = fmaf(ex1, Wo[1][1], fmaf(ex0, Wo[1][0], bo[1]));
        float gb1 = fmaf(ex3, Wo[1][3], ex2 * Wo[1][2]);
        float act0 = fmaf(A1c, tanhap(ga0 + gb0), A2c);
        float act1 = fmaf(A1c, tanhap(ga1 + gb1), A2c);

        // ---- S4: gather f,i,u,o (one stage, 8 idx shfls); cell update ----
        {
            const int s0 = b16 + sub;
            float fv0 = __shfl_sync(FULL, act0, s0);
            float fv1 = __shfl_sync(FULL, act1, s0);
            float iv0 = __shfl_sync(FULL, act0, s0 + 4);
            float iv1 = __shfl_sync(FULL, act1, s0 + 4);
            float uv0 = __shfl_sync(FULL, act0, s0 + 8);
            float uv1 = __shfl_sync(FULL, act1, s0 + 8);
            float ov0 = __shfl_sync(FULL, act0, s0 + 12);
            float ov1 = __shfl_sync(FULL, act1, s0 + 12);

            cc0 = fmaf(fv0, cc0, iv0 * uv0);
            cc1 = fmaf(fv1, cc1, iv1 * uv1);
            h0 = ov0 * tanhap(cc0);
            h1 = ov1 * tanhap(cc1);
        }
    }

    // ---- final projection (own comps; reduce over sub lanes) ----
    float p = h0 * __ldg(&w_fc[2 * sub]);
    p = fmaf(h1, __ldg(&w_fc[2 * sub + 1]), p);
    p += sx(p, 1);
    p += sx(p, 2);
    if (gl == 0 && e0 < B) out[e0] = p + __ldg(&b_fc[0]);
}

extern "C" void kernel_launch(void* const* d_in, const int* in_sizes, int n_in,
                              void* d_out, int out_size) {
    const float* x     = (const float*)d_in[0];
    const float* w_in  = (const float*)d_in[1];
    const float* b_in  = (const float*)d_in[2];
    const float* w_out = (const float*)d_in[3];
    const float* b_out = (const float*)d_in[4];
    const float* wq_f  = (const float*)d_in[5];
    const float* wq_i  = (const float*)d_in[6];
    const float* wq_u  = (const float*)d_in[7];
    const float* wq_o  = (const float*)d_in[8];
    const float* w_fc  = (const float*)d_in[9];
    const float* b_fc  = (const float*)d_in[10];

    int B = in_sizes[0] / (TT * 32);
    int threads = B * 16;
    int blocks = (threads + 127) / 128;
    qlstm4s<<<blocks, 128>>>(x, w_in, b_in, w_out, b_out,
                             wq_f, wq_i, wq_u, wq_o, w_fc, b_fc,
                             (float*)d_out, B);
}